// round 1
// baseline (speedup 1.0000x reference)
#include <cuda_runtime.h>
#include <math.h>

// Problem constants
#define D_DIM 1024
#define H_DIM 512
#define E_NUM 16
#define NTOK  4096
#define KSEL  8
#define NK    (NTOK * KSEL)

// ---------------------------------------------------------------------------
// Device scratch (static globals: allocation-free per harness rules)
// ---------------------------------------------------------------------------
__device__ float g_gwn[E_NUM * D_DIM];      // normalized gate_w
__device__ int   g_idx[NK];                 // per (token,k) expert index
__device__ float g_w[NK];                   // per (token,k) combine weight
__device__ int   g_cnt[E_NUM];
__device__ int   g_off[E_NUM];
__device__ int   g_pos[E_NUM];
__device__ int   g_tok[NK];                 // token ids grouped by expert
__device__ float g_tw[NK];                  // matching combine weights
__device__ float g_h[(size_t)NK * H_DIM];   // routed hidden (weighted) 64 MB
__device__ float g_hs[(size_t)NTOK * H_DIM];// shared-expert hidden 8 MB

// ---------------------------------------------------------------------------
// Small kernels
// ---------------------------------------------------------------------------
__global__ void init_kernel() {
    if (threadIdx.x < E_NUM) g_cnt[threadIdx.x] = 0;
}

__global__ void gwnorm_kernel(const float* __restrict__ gw) {
    int e = blockIdx.x;
    int t = threadIdx.x;
    __shared__ float red[8];
    float ss = 0.f;
    for (int i = t; i < D_DIM; i += 256) {
        float v = gw[e * D_DIM + i];
        ss += v * v;
    }
    for (int o = 16; o; o >>= 1) ss += __shfl_down_sync(0xFFFFFFFFu, ss, o);
    if ((t & 31) == 0) red[t >> 5] = ss;
    __syncthreads();
    __shared__ float s_inv;
    if (t == 0) {
        float tot = 0.f;
        for (int i = 0; i < 8; i++) tot += red[i];
        s_inv = 1.0f / fmaxf(sqrtf(tot), 1e-12f);
    }
    __syncthreads();
    float inv = s_inv;
    for (int i = t; i < D_DIM; i += 256) g_gwn[e * D_DIM + i] = gw[e * D_DIM + i] * inv;
}

// One block per token: norm, 16 cosine logits, sigmoid, top-8, L1 weights.
__global__ void gating_kernel(const float* __restrict__ x) {
    int n = blockIdx.x;
    int t = threadIdx.x;
    int warp = t >> 5, lane = t & 31;
    __shared__ float sx[D_DIM];
    __shared__ float red[8];
    __shared__ float slog[E_NUM];

    const float* xr = x + (size_t)n * D_DIM;
    float ss = 0.f;
    for (int i = t; i < D_DIM; i += 256) {
        float v = xr[i];
        sx[i] = v;
        ss += v * v;
    }
    for (int o = 16; o; o >>= 1) ss += __shfl_down_sync(0xFFFFFFFFu, ss, o);
    if (lane == 0) red[warp] = ss;
    __syncthreads();

    // each warp handles 2 experts' dot products
    for (int j = 0; j < 2; j++) {
        int e = warp * 2 + j;
        const float* g = g_gwn + e * D_DIM;
        float d = 0.f;
        for (int i = lane; i < D_DIM; i += 32) d += sx[i] * g[i];
        for (int o = 16; o; o >>= 1) d += __shfl_down_sync(0xFFFFFFFFu, d, o);
        if (lane == 0) slog[e] = d;
    }
    __syncthreads();

    if (t == 0) {
        float ssq = 0.f;
        for (int i = 0; i < 8; i++) ssq += red[i];
        float inv = 1.0f / fmaxf(sqrtf(ssq), 1e-12f);
        float sc[E_NUM];
        for (int e = 0; e < E_NUM; e++) sc[e] = slog[e] * inv;  // logits (monotone w/ scores)
        int   sel[KSEL];
        float sw[KSEL];
        float wsum = 0.f;
        for (int k = 0; k < KSEL; k++) {
            int bi = 0;
            float bv = -1e30f;
            for (int e = 0; e < E_NUM; e++)
                if (sc[e] > bv) { bv = sc[e]; bi = e; }   // strict > : first-index tiebreak
            sel[k] = bi;
            float s = 1.0f / (1.0f + __expf(-bv));        // sigmoid of selected logit
            sw[k] = s;
            wsum += s;
            sc[bi] = -1e30f;
        }
        float invw = 1.0f / wsum;
        for (int k = 0; k < KSEL; k++) {
            g_idx[n * KSEL + k] = sel[k];
            g_w[n * KSEL + k]   = sw[k] * invw;
            atomicAdd(&g_cnt[sel[k]], 1);
        }
    }
}

__global__ void scan_kernel() {
    if (threadIdx.x == 0) {
        int a = 0;
        for (int e = 0; e < E_NUM; e++) {
            g_off[e] = a;
            a += g_cnt[e];
            g_pos[e] = 0;
        }
    }
}

__global__ void scatter_kernel() {
    int id = blockIdx.x * 256 + threadIdx.x;
    if (id < NK) {
        int e = g_idx[id];
        int p = g_off[e] + atomicAdd(&g_pos[e], 1);
        g_tok[p] = id / KSEL;
        g_tw[p]  = g_w[id];
    }
}

// ---------------------------------------------------------------------------
// Gate+Up GEMM:  h[row, n0:n0+64] = tw * silu(x@Wg) * (x@Wu)
// BM=64 BN=64 BK=16, 256 threads, 4x4 microtile.
// GATHER=true : rows are g_tok[] tokens of expert blockIdx.z, output g_h
// GATHER=false: rows are tokens 0..4095 (shared expert, z=0), output g_hs
// ---------------------------------------------------------------------------
template <bool GATHER>
__global__ void __launch_bounds__(256, 2)
gateup_kernel(const float* __restrict__ x,
              const float* __restrict__ wg,
              const float* __restrict__ wu) {
    const int e   = blockIdx.z;
    const int cnt = GATHER ? g_cnt[e] : NTOK;
    const int m0  = blockIdx.x * 64;
    if (m0 >= cnt) return;
    const int off = GATHER ? g_off[e] : 0;
    const int n0  = blockIdx.y * 64;

    const float* Bg0 = wg + (size_t)e * D_DIM * H_DIM;
    const float* Bu0 = wu + (size_t)e * D_DIM * H_DIM;
    float* hout = GATHER ? g_h : g_hs;

    __shared__ float As[64][20];    // [m][k], padded
    __shared__ float Bgs[16][64];   // [k][n]
    __shared__ float Bus[16][64];

    const int t  = threadIdx.x;
    const int tx = t & 15, ty = t >> 4;

    // A-load: thread loads float4 at row lr, cols lc..lc+3
    const int lr = t >> 2;
    const int lc = (t & 3) * 4;
    const int arow = m0 + lr;
    int tok = -1;
    if (arow < cnt) tok = GATHER ? g_tok[off + arow] : arow;
    const float* arowp = x + (size_t)(tok < 0 ? 0 : tok) * D_DIM;

    // B-load: row br, cols bc..bc+3
    const int br = t >> 4;
    const int bc = (t & 15) * 4;

    float accg[4][4] = {};
    float accu[4][4] = {};

    for (int k0 = 0; k0 < D_DIM; k0 += 16) {
        float4 av = make_float4(0.f, 0.f, 0.f, 0.f);
        if (tok >= 0) av = *(const float4*)(arowp + k0 + lc);
        *(float4*)&As[lr][lc] = av;
        *(float4*)&Bgs[br][bc] = *(const float4*)(Bg0 + (size_t)(k0 + br) * H_DIM + n0 + bc);
        *(float4*)&Bus[br][bc] = *(const float4*)(Bu0 + (size_t)(k0 + br) * H_DIM + n0 + bc);
        __syncthreads();
#pragma unroll
        for (int k = 0; k < 16; k++) {
            float a[4];
#pragma unroll
            for (int i = 0; i < 4; i++) a[i] = As[ty * 4 + i][k];
            float4 bg = *(float4*)&Bgs[k][tx * 4];
            float4 bu = *(float4*)&Bus[k][tx * 4];
#pragma unroll
            for (int i = 0; i < 4; i++) {
                accg[i][0] += a[i] * bg.x; accg[i][1] += a[i] * bg.y;
                accg[i][2] += a[i] * bg.z; accg[i][3] += a[i] * bg.w;
                accu[i][0] += a[i] * bu.x; accu[i][1] += a[i] * bu.y;
                accu[i][2] += a[i] * bu.z; accu[i][3] += a[i] * bu.w;
            }
        }
        __syncthreads();
    }

#pragma unroll
    for (int i = 0; i < 4; i++) {
        int gm = m0 + ty * 4 + i;
        if (gm < cnt) {
            float tw = GATHER ? g_tw[off + gm] : 1.0f;
            float4 o;
            float g, u;
            g = accg[i][0]; u = accu[i][0]; o.x = tw * u * g / (1.0f + __expf(-g));
            g = accg[i][1]; u = accu[i][1]; o.y = tw * u * g / (1.0f + __expf(-g));
            g = accg[i][2]; u = accu[i][2]; o.z = tw * u * g / (1.0f + __expf(-g));
            g = accg[i][3]; u = accu[i][3]; o.w = tw * u * g / (1.0f + __expf(-g));
            *(float4*)(hout + (size_t)(off + gm) * H_DIM + n0 + tx * 4) = o;
        }
    }
}

// ---------------------------------------------------------------------------
// Down GEMM:  y[row, n0:n0+64] = h@Wd ; GATHER: atomicAdd into out[token],
// else plain store (shared expert initializes out).
// K = H_DIM = 512, N = D_DIM = 1024.
// ---------------------------------------------------------------------------
template <bool GATHER>
__global__ void __launch_bounds__(256, 2)
down_kernel(const float* __restrict__ wd, float* __restrict__ out) {
    const int e   = blockIdx.z;
    const int cnt = GATHER ? g_cnt[e] : NTOK;
    const int m0  = blockIdx.x * 64;
    if (m0 >= cnt) return;
    const int off = GATHER ? g_off[e] : 0;
    const int n0  = blockIdx.y * 64;

    const float* B0  = wd + (size_t)e * H_DIM * D_DIM;
    const float* hin = GATHER ? g_h : g_hs;

    __shared__ float As[64][20];
    __shared__ float Bs[16][64];

    const int t  = threadIdx.x;
    const int tx = t & 15, ty = t >> 4;

    const int lr = t >> 2;
    const int lc = (t & 3) * 4;
    const int arow = m0 + lr;
    const bool aval = arow < cnt;
    const float* arowp = hin + (size_t)(off + (aval ? arow : 0)) * H_DIM;

    const int br = t >> 4;
    const int bc = (t & 15) * 4;

    float acc[4][4] = {};

    for (int k0 = 0; k0 < H_DIM; k0 += 16) {
        float4 av = make_float4(0.f, 0.f, 0.f, 0.f);
        if (aval) av = *(const float4*)(arowp + k0 + lc);
        *(float4*)&As[lr][lc] = av;
        *(float4*)&Bs[br][bc] = *(const float4*)(B0 + (size_t)(k0 + br) * D_DIM + n0 + bc);
        __syncthreads();
#pragma unroll
        for (int k = 0; k < 16; k++) {
            float a[4];
#pragma unroll
            for (int i = 0; i < 4; i++) a[i] = As[ty * 4 + i][k];
            float4 b = *(float4*)&Bs[k][tx * 4];
#pragma unroll
            for (int i = 0; i < 4; i++) {
                acc[i][0] += a[i] * b.x; acc[i][1] += a[i] * b.y;
                acc[i][2] += a[i] * b.z; acc[i][3] += a[i] * b.w;
            }
        }
        __syncthreads();
    }

#pragma unroll
    for (int i = 0; i < 4; i++) {
        int gm = m0 + ty * 4 + i;
        if (gm < cnt) {
            if (GATHER) {
                int tok = g_tok[off + gm];
                float* op = out + (size_t)tok * D_DIM + n0 + tx * 4;
                atomicAdd(op + 0, acc[i][0]);
                atomicAdd(op + 1, acc[i][1]);
                atomicAdd(op + 2, acc[i][2]);
                atomicAdd(op + 3, acc[i][3]);
            } else {
                *(float4*)(out + (size_t)gm * D_DIM + n0 + tx * 4) =
                    make_float4(acc[i][0], acc[i][1], acc[i][2], acc[i][3]);
            }
        }
    }
}

// ---------------------------------------------------------------------------
// Launch
// ---------------------------------------------------------------------------
extern "C" void kernel_launch(void* const* d_in, const int* in_sizes, int n_in,
                              void* d_out, int out_size) {
    (void)in_sizes; (void)n_in; (void)out_size;
    const float* x       = (const float*)d_in[0];
    const float* gate_w  = (const float*)d_in[1];
    const float* w_gate  = (const float*)d_in[2];
    const float* w_up    = (const float*)d_in[3];
    const float* w_down  = (const float*)d_in[4];
    const float* sw_gate = (const float*)d_in[5];
    const float* sw_up   = (const float*)d_in[6];
    const float* sw_down = (const float*)d_in[7];
    float* out = (float*)d_out;

    init_kernel<<<1, 32>>>();
    gwnorm_kernel<<<E_NUM, 256>>>(gate_w);
    gating_kernel<<<NTOK, 256>>>(x);
    scan_kernel<<<1, 32>>>();
    scatter_kernel<<<(NK + 255) / 256, 256>>>();

    // shared expert (initializes out with plain stores)
    gateup_kernel<false><<<dim3(NTOK / 64, H_DIM / 64, 1), 256>>>(x, sw_gate, sw_up);
    down_kernel<false><<<dim3(NTOK / 64, D_DIM / 64, 1), 256>>>(sw_down, out);

    // routed experts (accumulate into out)
    gateup_kernel<true><<<dim3(NTOK / 64, H_DIM / 64, E_NUM), 256>>>(x, w_gate, w_up);
    down_kernel<true><<<dim3(NTOK / 64, D_DIM / 64, E_NUM), 256>>>(w_down, out);
}

// round 3
// speedup vs baseline: 3.7046x; 3.7046x over previous
#include <cuda_runtime.h>
#include <cstdint>
#include <math.h>

#define D_DIM 1024
#define H_DIM 512
#define E_NUM 16
#define NTOK  4096
#define KSEL  8
#define NK    (NTOK * KSEL)

// ---------------------------------------------------------------------------
// Device scratch
// ---------------------------------------------------------------------------
__device__ float g_gwn[E_NUM * D_DIM];
__device__ int   g_idx[NK];
__device__ float g_w[NK];
__device__ int   g_cnt[E_NUM];
__device__ int   g_off[E_NUM];
__device__ int   g_pos[E_NUM];
__device__ int   g_tok[NK + 128];
__device__ float g_tw[NK + 128];
__device__ int   g_pmap[NK];

__device__ float g_xt[(size_t)NTOK * D_DIM];              // tf32-rounded x
__device__ float g_wguT[(size_t)E_NUM * 2 * H_DIM * D_DIM]; // [E][2H][D] interleaved gate/up, tf32
__device__ float g_wdT [(size_t)E_NUM * D_DIM * H_DIM];     // [E][D][H] tf32
__device__ float g_swguT[(size_t)2 * H_DIM * D_DIM];
__device__ float g_swdT [(size_t)D_DIM * H_DIM];

__device__ float g_h [((size_t)NK + 128) * H_DIM];        // routed hidden (weighted, tf32-rounded)
__device__ float g_hs[(size_t)NTOK * H_DIM];              // shared hidden (tf32-rounded)
__device__ float g_y [(size_t)NK * D_DIM];                // routed down output

// ---------------------------------------------------------------------------
// Helpers (sm_80-compatible PTX only)
// ---------------------------------------------------------------------------
__device__ __forceinline__ uint32_t smem_u32(const void* p) {
    uint32_t a;
    asm("{ .reg .u64 t; cvta.to.shared.u64 t, %1; cvt.u32.u64 %0, t; }" : "=r"(a) : "l"(p));
    return a;
}
__device__ __forceinline__ void cp16(uint32_t dst, const void* src) {
    asm volatile("cp.async.cg.shared.global [%0], [%1], 16;" :: "r"(dst), "l"(src));
}
#define CP_COMMIT() asm volatile("cp.async.commit_group;" ::: "memory")
#define CP_WAIT1()  asm volatile("cp.async.wait_group 1;" ::: "memory")
#define CP_WAIT0()  asm volatile("cp.async.wait_group 0;" ::: "memory")

__device__ __forceinline__ float tf32r(float f) {
    uint32_t o;
    asm("cvt.rna.tf32.f32 %0, %1;" : "=r"(o) : "f"(f));
    return __uint_as_float(o);
}
__device__ __forceinline__ void ldm4(uint32_t& r0, uint32_t& r1, uint32_t& r2, uint32_t& r3,
                                     uint32_t a) {
    asm volatile("ldmatrix.sync.aligned.m8n8.x4.shared.b16 {%0,%1,%2,%3}, [%4];"
                 : "=r"(r0), "=r"(r1), "=r"(r2), "=r"(r3) : "r"(a));
}
__device__ __forceinline__ void mma8(float* c, const uint32_t* a, uint32_t b0, uint32_t b1) {
    asm volatile("mma.sync.aligned.m16n8k8.row.col.f32.tf32.tf32.f32 "
                 "{%0,%1,%2,%3}, {%4,%5,%6,%7}, {%8,%9}, {%0,%1,%2,%3};"
                 : "+f"(c[0]), "+f"(c[1]), "+f"(c[2]), "+f"(c[3])
                 : "r"(a[0]), "r"(a[1]), "r"(a[2]), "r"(a[3]), "r"(b0), "r"(b1));
}

// ---------------------------------------------------------------------------
// Gating path (exact fp32 — must match reference routing)
// ---------------------------------------------------------------------------
__global__ void init_kernel() {
    if (threadIdx.x < E_NUM) g_cnt[threadIdx.x] = 0;
}

__global__ void gwnorm_kernel(const float* __restrict__ gw) {
    int e = blockIdx.x, t = threadIdx.x;
    __shared__ float red[8];
    float ss = 0.f;
    for (int i = t; i < D_DIM; i += 256) { float v = gw[e * D_DIM + i]; ss += v * v; }
    for (int o = 16; o; o >>= 1) ss += __shfl_down_sync(0xFFFFFFFFu, ss, o);
    if ((t & 31) == 0) red[t >> 5] = ss;
    __syncthreads();
    __shared__ float s_inv;
    if (t == 0) {
        float tot = 0.f;
        for (int i = 0; i < 8; i++) tot += red[i];
        s_inv = 1.0f / fmaxf(sqrtf(tot), 1e-12f);
    }
    __syncthreads();
    float inv = s_inv;
    for (int i = t; i < D_DIM; i += 256) g_gwn[e * D_DIM + i] = gw[e * D_DIM + i] * inv;
}

__global__ void gating_kernel(const float* __restrict__ x) {
    int n = blockIdx.x, t = threadIdx.x;
    int warp = t >> 5, lane = t & 31;
    __shared__ float sx[D_DIM];
    __shared__ float red[8];
    __shared__ float slog[E_NUM];
    const float* xr = x + (size_t)n * D_DIM;
    float ss = 0.f;
    for (int i = t; i < D_DIM; i += 256) { float v = xr[i]; sx[i] = v; ss += v * v; }
    for (int o = 16; o; o >>= 1) ss += __shfl_down_sync(0xFFFFFFFFu, ss, o);
    if (lane == 0) red[warp] = ss;
    __syncthreads();
    for (int j = 0; j < 2; j++) {
        int e = warp * 2 + j;
        const float* g = g_gwn + e * D_DIM;
        float d = 0.f;
        for (int i = lane; i < D_DIM; i += 32) d += sx[i] * g[i];
        for (int o = 16; o; o >>= 1) d += __shfl_down_sync(0xFFFFFFFFu, d, o);
        if (lane == 0) slog[e] = d;
    }
    __syncthreads();
    if (t == 0) {
        float ssq = 0.f;
        for (int i = 0; i < 8; i++) ssq += red[i];
        float inv = 1.0f / fmaxf(sqrtf(ssq), 1e-12f);
        float sc[E_NUM];
        for (int e = 0; e < E_NUM; e++) sc[e] = slog[e] * inv;
        int sel[KSEL]; float sw[KSEL]; float wsum = 0.f;
        for (int k = 0; k < KSEL; k++) {
            int bi = 0; float bv = -1e30f;
            for (int e = 0; e < E_NUM; e++)
                if (sc[e] > bv) { bv = sc[e]; bi = e; }
            sel[k] = bi;
            float s = 1.0f / (1.0f + __expf(-bv));
            sw[k] = s; wsum += s; sc[bi] = -1e30f;
        }
        float invw = 1.0f / wsum;
        for (int k = 0; k < KSEL; k++) {
            g_idx[n * KSEL + k] = sel[k];
            g_w[n * KSEL + k]   = sw[k] * invw;
            atomicAdd(&g_cnt[sel[k]], 1);
        }
    }
}

__global__ void scan_kernel() {
    if (threadIdx.x == 0) {
        int a = 0;
        for (int e = 0; e < E_NUM; e++) { g_off[e] = a; a += g_cnt[e]; g_pos[e] = 0; }
    }
}

__global__ void scatter_kernel() {
    int id = blockIdx.x * 256 + threadIdx.x;
    if (id < NK) {
        int e = g_idx[id];
        int p = g_off[e] + atomicAdd(&g_pos[e], 1);
        g_tok[p] = id / KSEL;
        g_tw[p]  = g_w[id];
        g_pmap[id] = p;
    }
}

// ---------------------------------------------------------------------------
// Transpose + tf32-round (+interleave): src [z][R][C] -> dst row (c*mul+add)
// dst batch stride = R*C*mul, dst row stride = R.
// ---------------------------------------------------------------------------
__global__ void transpose_kernel(const float* __restrict__ src, float* __restrict__ dst,
                                 int R, int C, int mul, int add) {
    __shared__ float tile[32][33];
    size_t bi = (size_t)blockIdx.z * R * C;
    size_t bo = (size_t)blockIdx.z * R * C * mul;
    int c0 = blockIdx.x * 32, r0 = blockIdx.y * 32;
    int tx = threadIdx.x, ty = threadIdx.y;
#pragma unroll
    for (int j = 0; j < 32; j += 8)
        tile[ty + j][tx] = src[bi + (size_t)(r0 + ty + j) * C + c0 + tx];
    __syncthreads();
#pragma unroll
    for (int j = 0; j < 32; j += 8)
        dst[bo + (size_t)((c0 + ty + j) * mul + add) * R + r0 + tx] = tf32r(tile[tx][ty + j]);
}

__global__ void xcvt_kernel(const float* __restrict__ x) {
    int i = blockIdx.x * 256 + threadIdx.x;
    float4 v = ((const float4*)x)[i];
    v.x = tf32r(v.x); v.y = tf32r(v.y); v.z = tf32r(v.z); v.w = tf32r(v.w);
    ((float4*)g_xt)[i] = v;
}

// ---------------------------------------------------------------------------
// tf32 mma.sync GEMM. Block 128x128, BK=32, 256 threads, warp grid 2(m)x4(n),
// warp tile 64x32 -> 4x4 m16n8k8 mma tiles. A: [M][K] gathered rows,
// B: [1024][K] per expert (GU: interleaved gate/up rows; DN: w_down^T).
// GU epilogue: silu(gate)*up*tw -> h (tf32-rounded). DN: plain store.
// ---------------------------------------------------------------------------
#define TSTRIDE 36           // padded row stride (floats)
#define TILE_F  (128 * TSTRIDE)
#define TILE_B  (TILE_F * 4)
#define SMEM_BYTES (4 * TILE_B + 128 * 8)

template <bool GATHER, bool GU>
__global__ void __launch_bounds__(256)
mma_gemm(const float* __restrict__ A, const float* __restrict__ B, float* __restrict__ out) {
    constexpr int KD = GU ? D_DIM : H_DIM;
    const int e   = blockIdx.z;
    const int cnt = GATHER ? g_cnt[e] : NTOK;
    const int m0  = blockIdx.x * 128;
    if (m0 >= cnt) return;
    const int off = GATHER ? g_off[e] : 0;
    const int n0  = blockIdx.y * 128;

    extern __shared__ float smf[];
    float* As = smf;                       // 2 stages of TILE_F
    float* Bs = smf + 2 * TILE_F;
    int*   rtok = (int*)(smf + 4 * TILE_F);
    float* twsh = smf + 4 * TILE_F + 128;

    const int t = threadIdx.x;
    const int warp = t >> 5, lane = t & 31;
    const int wm = warp >> 2, wn = warp & 3;   // 2 x 4

    // A source row indices + combine weights
    if (t < 128) {
        int gm = m0 + t;
        int cg = (gm < cnt) ? gm : 0;
        int src;
        if (GU) src = GATHER ? g_tok[off + cg] : gm;
        else    src = (GATHER ? off : 0) + gm;
        rtok[t] = src;
        twsh[t] = (GU && GATHER) ? g_tw[off + cg] : 1.0f;
    }
    __syncthreads();

    const uint32_t uA = smem_u32(As);
    const uint32_t uB = smem_u32(Bs);

    // per-thread load assignments: 4 (row, kc) pairs for A and B each
    const size_t eoff = GATHER ? (size_t)e * 1024 * KD : 0;
    const float* aP[4];
    const float* bP[4];
    uint32_t sOff[4];
#pragma unroll
    for (int j = 0; j < 4; j++) {
        int cidx = t + j * 256;
        int row = cidx >> 3, kc = cidx & 7;
        aP[j] = A + (size_t)rtok[row] * KD + kc * 4;
        bP[j] = B + eoff + (size_t)(n0 + row) * KD + kc * 4;
        sOff[j] = (uint32_t)(row * (TSTRIDE * 4) + kc * 16);
    }

#define LOADSTAGE(s, k0) do {                                       \
        _Pragma("unroll")                                           \
        for (int j = 0; j < 4; j++) {                               \
            cp16(uA + (s) * TILE_B + sOff[j], aP[j] + (k0));        \
            cp16(uB + (s) * TILE_B + sOff[j], bP[j] + (k0));        \
        }                                                           \
        CP_COMMIT();                                                \
    } while (0)

    float c[4][4][4] = {};

    const int NIT = KD / 32;
    LOADSTAGE(0, 0);

    for (int i = 0; i < NIT; i++) {
        if (i + 1 < NIT) { LOADSTAGE((i + 1) & 1, (i + 1) * 32); CP_WAIT1(); }
        else             { CP_WAIT0(); }
        __syncthreads();

        const uint32_t uAs = uA + (i & 1) * TILE_B;
        const uint32_t uBs = uB + (i & 1) * TILE_B;
#pragma unroll
        for (int ks = 0; ks < 4; ks++) {
            uint32_t a[4][4], b[2][4];
#pragma unroll
            for (int mt = 0; mt < 4; mt++) {
                uint32_t row = wm * 64 + mt * 16 + (lane & 7) + ((lane >> 3) & 1) * 8;
                uint32_t ad = uAs + row * (TSTRIDE * 4) + ks * 32 + (lane >> 4) * 16;
                ldm4(a[mt][0], a[mt][1], a[mt][2], a[mt][3], ad);
            }
#pragma unroll
            for (int p = 0; p < 2; p++) {
                uint32_t row = wn * 32 + p * 16 + ((lane >> 4) & 1) * 8 + (lane & 7);
                uint32_t ad = uBs + row * (TSTRIDE * 4) + ks * 32 + ((lane >> 3) & 1) * 16;
                ldm4(b[p][0], b[p][1], b[p][2], b[p][3], ad);
            }
#pragma unroll
            for (int mt = 0; mt < 4; mt++) {
#pragma unroll
                for (int nt = 0; nt < 4; nt++)
                    mma8(c[mt][nt], a[mt], b[nt >> 1][2 * (nt & 1)], b[nt >> 1][2 * (nt & 1) + 1]);
            }
        }
        __syncthreads();
    }
#undef LOADSTAGE

    // epilogue
    const int obase_row = GATHER ? off : 0;
#pragma unroll
    for (int mt = 0; mt < 4; mt++) {
        int r0 = wm * 64 + mt * 16 + (lane >> 2);
#pragma unroll
        for (int pass = 0; pass < 2; pass++) {
            int r = r0 + pass * 8;
            int gm = m0 + r;
            if (gm < cnt) {
                if (GU) {
                    float tw = twsh[r];
                    float* orow = out + (size_t)(obase_row + gm) * H_DIM;
#pragma unroll
                    for (int nt = 0; nt < 4; nt++) {
                        float g = c[mt][nt][pass * 2];
                        float u = c[mt][nt][pass * 2 + 1];
                        int h = (n0 + wn * 32 + nt * 8) / 2 + (lane & 3);
                        orow[h] = tf32r(tw * u * g / (1.0f + __expf(-g)));
                    }
                } else {
                    float* orow = out + (size_t)(obase_row + gm) * D_DIM;
#pragma unroll
                    for (int nt = 0; nt < 4; nt++) {
                        int n = n0 + wn * 32 + nt * 8 + 2 * (lane & 3);
                        float2 v = make_float2(c[mt][nt][pass * 2], c[mt][nt][pass * 2 + 1]);
                        *(float2*)(orow + n) = v;
                    }
                }
            }
        }
    }
}

// ---------------------------------------------------------------------------
// combine: out[n] += sum_k g_y[pmap[n,k]]
// ---------------------------------------------------------------------------
__global__ void combine_kernel(float* __restrict__ out) {
    const int n = blockIdx.x, t = threadIdx.x;
    __shared__ int pm[KSEL];
    if (t < KSEL) pm[t] = g_pmap[n * KSEL + t];
    __syncthreads();
    float4 acc = *(const float4*)(out + (size_t)n * D_DIM + t * 4);
#pragma unroll
    for (int k = 0; k < KSEL; k++) {
        float4 v = *(const float4*)(g_y + (size_t)pm[k] * D_DIM + t * 4);
        acc.x += v.x; acc.y += v.y; acc.z += v.z; acc.w += v.w;
    }
    *(float4*)(out + (size_t)n * D_DIM + t * 4) = acc;
}

// ---------------------------------------------------------------------------
// Launch
// ---------------------------------------------------------------------------
extern "C" void kernel_launch(void* const* d_in, const int* in_sizes, int n_in,
                              void* d_out, int out_size) {
    (void)in_sizes; (void)n_in; (void)out_size;
    const float* x       = (const float*)d_in[0];
    const float* gate_w  = (const float*)d_in[1];
    const float* w_gate  = (const float*)d_in[2];
    const float* w_up    = (const float*)d_in[3];
    const float* w_down  = (const float*)d_in[4];
    const float* sw_gate = (const float*)d_in[5];
    const float* sw_up   = (const float*)d_in[6];
    const float* sw_down = (const float*)d_in[7];
    float* out = (float*)d_out;

    cudaFuncSetAttribute(mma_gemm<true, true>,   cudaFuncAttributeMaxDynamicSharedMemorySize, SMEM_BYTES);
    cudaFuncSetAttribute(mma_gemm<true, false>,  cudaFuncAttributeMaxDynamicSharedMemorySize, SMEM_BYTES);
    cudaFuncSetAttribute(mma_gemm<false, true>,  cudaFuncAttributeMaxDynamicSharedMemorySize, SMEM_BYTES);
    cudaFuncSetAttribute(mma_gemm<false, false>, cudaFuncAttributeMaxDynamicSharedMemorySize, SMEM_BYTES);

    float* xt; float* wguT; float* wdT; float* swguT; float* swdT;
    float* hbuf; float* hsbuf; float* ybuf;
    cudaGetSymbolAddress((void**)&xt,    g_xt);
    cudaGetSymbolAddress((void**)&wguT,  g_wguT);
    cudaGetSymbolAddress((void**)&wdT,   g_wdT);
    cudaGetSymbolAddress((void**)&swguT, g_swguT);
    cudaGetSymbolAddress((void**)&swdT,  g_swdT);
    cudaGetSymbolAddress((void**)&hbuf,  g_h);
    cudaGetSymbolAddress((void**)&hsbuf, g_hs);
    cudaGetSymbolAddress((void**)&ybuf,  g_y);

    dim3 tb(32, 8);

    init_kernel<<<1, 32>>>();
    gwnorm_kernel<<<E_NUM, 256>>>(gate_w);
    gating_kernel<<<NTOK, 256>>>(x);
    scan_kernel<<<1, 32>>>();
    scatter_kernel<<<(NK + 255) / 256, 256>>>();

    xcvt_kernel<<<NTOK * D_DIM / 4 / 256, 256>>>(x);

    // weight prep: [D][H] -> interleaved [2H][D]; [H][D] -> [D][H]
    transpose_kernel<<<dim3(H_DIM / 32, D_DIM / 32, E_NUM), tb>>>(w_gate, wguT, D_DIM, H_DIM, 2, 0);
    transpose_kernel<<<dim3(H_DIM / 32, D_DIM / 32, E_NUM), tb>>>(w_up,   wguT, D_DIM, H_DIM, 2, 1);
    transpose_kernel<<<dim3(D_DIM / 32, H_DIM / 32, E_NUM), tb>>>(w_down, wdT,  H_DIM, D_DIM, 1, 0);
    transpose_kernel<<<dim3(H_DIM / 32, D_DIM / 32, 1), tb>>>(sw_gate, swguT, D_DIM, H_DIM, 2, 0);
    transpose_kernel<<<dim3(H_DIM / 32, D_DIM / 32, 1), tb>>>(sw_up,   swguT, D_DIM, H_DIM, 2, 1);
    transpose_kernel<<<dim3(D_DIM / 32, H_DIM / 32, 1), tb>>>(sw_down, swdT,  H_DIM, D_DIM, 1, 0);

    // shared expert (initializes out)
    mma_gemm<false, true><<<dim3(NTOK / 128, 8, 1), 256, SMEM_BYTES>>>(xt, swguT, hsbuf);
    mma_gemm<false, false><<<dim3(NTOK / 128, 8, 1), 256, SMEM_BYTES>>>(hsbuf, swdT, out);

    // routed experts
    mma_gemm<true, true><<<dim3(NTOK / 128, 8, E_NUM), 256, SMEM_BYTES>>>(xt, wguT, hbuf);
    mma_gemm<true, false><<<dim3(NTOK / 128, 8, E_NUM), 256, SMEM_BYTES>>>(hbuf, wdT, ybuf);

    combine_kernel<<<NTOK, 256>>>(out);
}

// round 4
// speedup vs baseline: 3.7049x; 1.0001x over previous
#include <cuda_runtime.h>
#include <cstdint>
#include <math.h>

#define D_DIM 1024
#define H_DIM 512
#define E_NUM 16
#define NTOK  4096
#define KSEL  8
#define NK    (NTOK * KSEL)

// ---------------------------------------------------------------------------
// Device scratch
// ---------------------------------------------------------------------------
__device__ float g_gwn[E_NUM * D_DIM];
__device__ int   g_idx[NK];
__device__ float g_w[NK];
__device__ int   g_cnt[E_NUM];
__device__ int   g_off[E_NUM];
__device__ int   g_pos[E_NUM];
__device__ int   g_tok[NK + 128];
__device__ float g_tw[NK + 128];
__device__ int   g_pmap[NK];

__device__ float g_xt[(size_t)NTOK * D_DIM];                // tf32-rounded x
__device__ float g_wguT[(size_t)E_NUM * 2 * H_DIM * D_DIM]; // [E][2H][D] interleaved gate/up
__device__ float g_wdT [(size_t)E_NUM * D_DIM * H_DIM];     // [E][D][H]
__device__ float g_swguT[(size_t)2 * H_DIM * D_DIM];
__device__ float g_swdT [(size_t)D_DIM * H_DIM];

__device__ float g_h [((size_t)NK + 128) * H_DIM];          // routed hidden (weighted, rounded)
__device__ float g_hs[(size_t)NTOK * H_DIM];                // shared hidden (rounded)
__device__ float g_y [(size_t)NK * D_DIM];                  // routed down output

// ---------------------------------------------------------------------------
// Helpers (sm_80-compatible PTX only — harness compiles for plain sm_100)
// ---------------------------------------------------------------------------
__device__ __forceinline__ uint32_t smem_u32(const void* p) {
    uint32_t a;
    asm("{ .reg .u64 t; cvta.to.shared.u64 t, %1; cvt.u32.u64 %0, t; }" : "=r"(a) : "l"(p));
    return a;
}
__device__ __forceinline__ void cp16(uint32_t dst, const void* src) {
    asm volatile("cp.async.cg.shared.global [%0], [%1], 16;" :: "r"(dst), "l"(src));
}
#define CP_COMMIT() asm volatile("cp.async.commit_group;" ::: "memory")
#define CP_WAIT1()  asm volatile("cp.async.wait_group 1;" ::: "memory")
#define CP_WAIT0()  asm volatile("cp.async.wait_group 0;" ::: "memory")

__device__ __forceinline__ float tf32r(float f) {
    uint32_t o;
    asm("cvt.rna.tf32.f32 %0, %1;" : "=r"(o) : "f"(f));
    return __uint_as_float(o);
}
__device__ __forceinline__ void ldm4(uint32_t& r0, uint32_t& r1, uint32_t& r2, uint32_t& r3,
                                     uint32_t a) {
    asm volatile("ldmatrix.sync.aligned.m8n8.x4.shared.b16 {%0,%1,%2,%3}, [%4];"
                 : "=r"(r0), "=r"(r1), "=r"(r2), "=r"(r3) : "r"(a));
}
__device__ __forceinline__ void mma8(float* c, const uint32_t* a, uint32_t b0, uint32_t b1) {
    asm volatile("mma.sync.aligned.m16n8k8.row.col.f32.tf32.tf32.f32 "
                 "{%0,%1,%2,%3}, {%4,%5,%6,%7}, {%8,%9}, {%0,%1,%2,%3};"
                 : "+f"(c[0]), "+f"(c[1]), "+f"(c[2]), "+f"(c[3])
                 : "r"(a[0]), "r"(a[1]), "r"(a[2]), "r"(a[3]), "r"(b0), "r"(b1));
}

// ---------------------------------------------------------------------------
// Gating path (exact fp32 — must match reference routing)
// ---------------------------------------------------------------------------
__global__ void gwnorm_kernel(const float* __restrict__ gw) {
    int e = blockIdx.x, t = threadIdx.x;
    if (e == 0 && t < E_NUM) g_cnt[t] = 0;          // folded init
    __shared__ float red[8];
    float ss = 0.f;
    for (int i = t; i < D_DIM; i += 256) { float v = gw[e * D_DIM + i]; ss += v * v; }
    for (int o = 16; o; o >>= 1) ss += __shfl_down_sync(0xFFFFFFFFu, ss, o);
    if ((t & 31) == 0) red[t >> 5] = ss;
    __syncthreads();
    __shared__ float s_inv;
    if (t == 0) {
        float tot = 0.f;
        for (int i = 0; i < 8; i++) tot += red[i];
        s_inv = 1.0f / fmaxf(sqrtf(tot), 1e-12f);
    }
    __syncthreads();
    float inv = s_inv;
    for (int i = t; i < D_DIM; i += 256) g_gwn[e * D_DIM + i] = gw[e * D_DIM + i] * inv;
}

// Also emits the tf32-rounded copy of x (g_xt) — saves a separate pass.
__global__ void gating_kernel(const float* __restrict__ x) {
    int n = blockIdx.x, t = threadIdx.x;
    int warp = t >> 5, lane = t & 31;
    __shared__ float sx[D_DIM];
    __shared__ float red[8];
    __shared__ float slog[E_NUM];
    const float* xr = x + (size_t)n * D_DIM;
    float ss = 0.f;
    for (int i = t; i < D_DIM; i += 256) { float v = xr[i]; sx[i] = v; ss += v * v; }
    for (int o = 16; o; o >>= 1) ss += __shfl_down_sync(0xFFFFFFFFu, ss, o);
    if (lane == 0) red[warp] = ss;
    __syncthreads();
    // rounded copy out (coalesced)
    for (int i = t; i < D_DIM; i += 256) g_xt[(size_t)n * D_DIM + i] = tf32r(sx[i]);
    for (int j = 0; j < 2; j++) {
        int e = warp * 2 + j;
        const float* g = g_gwn + e * D_DIM;
        float d = 0.f;
        for (int i = lane; i < D_DIM; i += 32) d += sx[i] * g[i];
        for (int o = 16; o; o >>= 1) d += __shfl_down_sync(0xFFFFFFFFu, d, o);
        if (lane == 0) slog[e] = d;
    }
    __syncthreads();
    if (t == 0) {
        float ssq = 0.f;
        for (int i = 0; i < 8; i++) ssq += red[i];
        float inv = 1.0f / fmaxf(sqrtf(ssq), 1e-12f);
        float sc[E_NUM];
        for (int e = 0; e < E_NUM; e++) sc[e] = slog[e] * inv;
        int sel[KSEL]; float sw[KSEL]; float wsum = 0.f;
        for (int k = 0; k < KSEL; k++) {
            int bi = 0; float bv = -1e30f;
            for (int e = 0; e < E_NUM; e++)
                if (sc[e] > bv) { bv = sc[e]; bi = e; }
            sel[k] = bi;
            float s = 1.0f / (1.0f + __expf(-bv));
            sw[k] = s; wsum += s; sc[bi] = -1e30f;
        }
        float invw = 1.0f / wsum;
        for (int k = 0; k < KSEL; k++) {
            g_idx[n * KSEL + k] = sel[k];
            g_w[n * KSEL + k]   = sw[k] * invw;
            atomicAdd(&g_cnt[sel[k]], 1);
        }
    }
}

__global__ void scan_kernel() {
    if (threadIdx.x == 0) {
        int a = 0;
        for (int e = 0; e < E_NUM; e++) { g_off[e] = a; a += g_cnt[e]; g_pos[e] = 0; }
    }
}

__global__ void scatter_kernel() {
    int id = blockIdx.x * 256 + threadIdx.x;
    if (id < NK) {
        int e = g_idx[id];
        int p = g_off[e] + atomicAdd(&g_pos[e], 1);
        g_tok[p] = id / KSEL;
        g_tw[p]  = g_w[id];
        g_pmap[id] = p;
    }
}

// ---------------------------------------------------------------------------
// Transpose + tf32-round (+interleave): src [z][R][C] -> dst row (c*mul+add)
// ---------------------------------------------------------------------------
__global__ void transpose_kernel(const float* __restrict__ src, float* __restrict__ dst,
                                 int R, int C, int mul, int add) {
    __shared__ float tile[32][33];
    size_t bi = (size_t)blockIdx.z * R * C;
    size_t bo = (size_t)blockIdx.z * R * C * mul;
    int c0 = blockIdx.x * 32, r0 = blockIdx.y * 32;
    int tx = threadIdx.x, ty = threadIdx.y;
#pragma unroll
    for (int j = 0; j < 32; j += 8)
        tile[ty + j][tx] = src[bi + (size_t)(r0 + ty + j) * C + c0 + tx];
    __syncthreads();
#pragma unroll
    for (int j = 0; j < 32; j += 8)
        dst[bo + (size_t)((c0 + ty + j) * mul + add) * R + r0 + tx] = tf32r(tile[tx][ty + j]);
}

// ---------------------------------------------------------------------------
// tf32 mma.sync GEMM. Block 128x128, BK=32, 256 threads, warp grid 2(m)x4(n),
// warp tile 64x32 -> 4x4 m16n8k8 tiles. 2 CTAs/SM for latency hiding.
// ---------------------------------------------------------------------------
#define TSTRIDE 36
#define TILE_F  (128 * TSTRIDE)
#define TILE_B  (TILE_F * 4)
#define SMEM_BYTES (4 * TILE_B + 128 * 8)

template <bool GATHER, bool GU>
__global__ void __launch_bounds__(256, 2)
mma_gemm(const float* __restrict__ A, const float* __restrict__ B, float* __restrict__ out) {
    constexpr int KD = GU ? D_DIM : H_DIM;
    const int e   = blockIdx.z;
    const int cnt = GATHER ? g_cnt[e] : NTOK;
    const int m0  = blockIdx.x * 128;
    if (m0 >= cnt) return;
    const int off = GATHER ? g_off[e] : 0;
    const int n0  = blockIdx.y * 128;

    extern __shared__ float smf[];
    float* As = smf;
    float* Bs = smf + 2 * TILE_F;
    int*   rtok = (int*)(smf + 4 * TILE_F);
    float* twsh = smf + 4 * TILE_F + 128;

    const int t = threadIdx.x;
    const int warp = t >> 5, lane = t & 31;
    const int wm = warp >> 2, wn = warp & 3;

    if (t < 128) {
        int gm = m0 + t;
        int cg = (gm < cnt) ? gm : 0;
        int src;
        if (GU) src = GATHER ? g_tok[off + cg] : gm;
        else    src = (GATHER ? off : 0) + gm;
        rtok[t] = src;
        twsh[t] = (GU && GATHER) ? g_tw[off + cg] : 1.0f;
    }
    __syncthreads();

    const uint32_t uA = smem_u32(As);
    const uint32_t uB = smem_u32(Bs);

    const size_t eoff = GATHER ? (size_t)e * 1024 * KD : 0;
    const float* aP[4];
    const float* bP[4];
    uint32_t sOff[4];
#pragma unroll
    for (int j = 0; j < 4; j++) {
        int cidx = t + j * 256;
        int row = cidx >> 3, kc = cidx & 7;
        aP[j] = A + (size_t)rtok[row] * KD + kc * 4;
        bP[j] = B + eoff + (size_t)(n0 + row) * KD + kc * 4;
        sOff[j] = (uint32_t)(row * (TSTRIDE * 4) + kc * 16);
    }

#define LOADSTAGE(s, k0) do {                                       \
        _Pragma("unroll")                                           \
        for (int j = 0; j < 4; j++) {                               \
            cp16(uA + (s) * TILE_B + sOff[j], aP[j] + (k0));        \
            cp16(uB + (s) * TILE_B + sOff[j], bP[j] + (k0));        \
        }                                                           \
        CP_COMMIT();                                                \
    } while (0)

    float c[4][4][4] = {};

    const int NIT = KD / 32;
    LOADSTAGE(0, 0);

    for (int i = 0; i < NIT; i++) {
        if (i + 1 < NIT) { LOADSTAGE((i + 1) & 1, (i + 1) * 32); CP_WAIT1(); }
        else             { CP_WAIT0(); }
        __syncthreads();

        const uint32_t uAs = uA + (i & 1) * TILE_B;
        const uint32_t uBs = uB + (i & 1) * TILE_B;
#pragma unroll
        for (int ks = 0; ks < 4; ks++) {
            uint32_t a[4][4], b[2][4];
#pragma unroll
            for (int mt = 0; mt < 4; mt++) {
                uint32_t row = wm * 64 + mt * 16 + (lane & 7) + ((lane >> 3) & 1) * 8;
                uint32_t ad = uAs + row * (TSTRIDE * 4) + ks * 32 + (lane >> 4) * 16;
                ldm4(a[mt][0], a[mt][1], a[mt][2], a[mt][3], ad);
            }
#pragma unroll
            for (int p = 0; p < 2; p++) {
                uint32_t row = wn * 32 + p * 16 + ((lane >> 4) & 1) * 8 + (lane & 7);
                uint32_t ad = uBs + row * (TSTRIDE * 4) + ks * 32 + ((lane >> 3) & 1) * 16;
                ldm4(b[p][0], b[p][1], b[p][2], b[p][3], ad);
            }
#pragma unroll
            for (int mt = 0; mt < 4; mt++) {
#pragma unroll
                for (int nt = 0; nt < 4; nt++)
                    mma8(c[mt][nt], a[mt], b[nt >> 1][2 * (nt & 1)], b[nt >> 1][2 * (nt & 1) + 1]);
            }
        }
        __syncthreads();
    }
#undef LOADSTAGE

    const int obase_row = GATHER ? off : 0;
#pragma unroll
    for (int mt = 0; mt < 4; mt++) {
        int r0 = wm * 64 + mt * 16 + (lane >> 2);
#pragma unroll
        for (int pass = 0; pass < 2; pass++) {
            int r = r0 + pass * 8;
            int gm = m0 + r;
            if (gm < cnt) {
                if (GU) {
                    float tw = twsh[r];
                    float* orow = out + (size_t)(obase_row + gm) * H_DIM;
#pragma unroll
                    for (int nt = 0; nt < 4; nt++) {
                        float g = c[mt][nt][pass * 2];
                        float u = c[mt][nt][pass * 2 + 1];
                        int h = (n0 + wn * 32 + nt * 8) / 2 + (lane & 3);
                        orow[h] = tf32r(tw * u * g / (1.0f + __expf(-g)));
                    }
                } else {
                    float* orow = out + (size_t)(obase_row + gm) * D_DIM;
#pragma unroll
                    for (int nt = 0; nt < 4; nt++) {
                        int n = n0 + wn * 32 + nt * 8 + 2 * (lane & 3);
                        float2 v = make_float2(c[mt][nt][pass * 2], c[mt][nt][pass * 2 + 1]);
                        *(float2*)(orow + n) = v;
                    }
                }
            }
        }
    }
}

// ---------------------------------------------------------------------------
// combine: out[n] += sum_k g_y[pmap[n,k]]
// ---------------------------------------------------------------------------
__global__ void combine_kernel(float* __restrict__ out) {
    const int n = blockIdx.x, t = threadIdx.x;
    __shared__ int pm[KSEL];
    if (t < KSEL) pm[t] = g_pmap[n * KSEL + t];
    __syncthreads();
    float4 acc = *(const float4*)(out + (size_t)n * D_DIM + t * 4);
#pragma unroll
    for (int k = 0; k < KSEL; k++) {
        float4 v = *(const float4*)(g_y + (size_t)pm[k] * D_DIM + t * 4);
        acc.x += v.x; acc.y += v.y; acc.z += v.z; acc.w += v.w;
    }
    *(float4*)(out + (size_t)n * D_DIM + t * 4) = acc;
}

// ---------------------------------------------------------------------------
// Launch
// ---------------------------------------------------------------------------
extern "C" void kernel_launch(void* const* d_in, const int* in_sizes, int n_in,
                              void* d_out, int out_size) {
    (void)in_sizes; (void)n_in; (void)out_size;
    const float* x       = (const float*)d_in[0];
    const float* gate_w  = (const float*)d_in[1];
    const float* w_gate  = (const float*)d_in[2];
    const float* w_up    = (const float*)d_in[3];
    const float* w_down  = (const float*)d_in[4];
    const float* sw_gate = (const float*)d_in[5];
    const float* sw_up   = (const float*)d_in[6];
    const float* sw_down = (const float*)d_in[7];
    float* out = (float*)d_out;

    cudaFuncSetAttribute(mma_gemm<true, true>,   cudaFuncAttributeMaxDynamicSharedMemorySize, SMEM_BYTES);
    cudaFuncSetAttribute(mma_gemm<true, false>,  cudaFuncAttributeMaxDynamicSharedMemorySize, SMEM_BYTES);
    cudaFuncSetAttribute(mma_gemm<false, true>,  cudaFuncAttributeMaxDynamicSharedMemorySize, SMEM_BYTES);
    cudaFuncSetAttribute(mma_gemm<false, false>, cudaFuncAttributeMaxDynamicSharedMemorySize, SMEM_BYTES);

    float* xt; float* wguT; float* wdT; float* swguT; float* swdT;
    float* hbuf; float* hsbuf; float* ybuf;
    cudaGetSymbolAddress((void**)&xt,    g_xt);
    cudaGetSymbolAddress((void**)&wguT,  g_wguT);
    cudaGetSymbolAddress((void**)&wdT,   g_wdT);
    cudaGetSymbolAddress((void**)&swguT, g_swguT);
    cudaGetSymbolAddress((void**)&swdT,  g_swdT);
    cudaGetSymbolAddress((void**)&hbuf,  g_h);
    cudaGetSymbolAddress((void**)&hsbuf, g_hs);
    cudaGetSymbolAddress((void**)&ybuf,  g_y);

    dim3 tb(32, 8);

    gwnorm_kernel<<<E_NUM, 256>>>(gate_w);
    gating_kernel<<<NTOK, 256>>>(x);
    scan_kernel<<<1, 32>>>();
    scatter_kernel<<<(NK + 255) / 256, 256>>>();

    // weight prep
    transpose_kernel<<<dim3(H_DIM / 32, D_DIM / 32, E_NUM), tb>>>(w_gate, wguT, D_DIM, H_DIM, 2, 0);
    transpose_kernel<<<dim3(H_DIM / 32, D_DIM / 32, E_NUM), tb>>>(w_up,   wguT, D_DIM, H_DIM, 2, 1);
    transpose_kernel<<<dim3(D_DIM / 32, H_DIM / 32, E_NUM), tb>>>(w_down, wdT,  H_DIM, D_DIM, 1, 0);
    transpose_kernel<<<dim3(H_DIM / 32, D_DIM / 32, 1), tb>>>(sw_gate, swguT, D_DIM, H_DIM, 2, 0);
    transpose_kernel<<<dim3(H_DIM / 32, D_DIM / 32, 1), tb>>>(sw_up,   swguT, D_DIM, H_DIM, 2, 1);
    transpose_kernel<<<dim3(D_DIM / 32, H_DIM / 32, 1), tb>>>(sw_down, swdT,  H_DIM, D_DIM, 1, 0);

    // shared expert (initializes out)
    mma_gemm<false, true><<<dim3(NTOK / 128, 8, 1), 256, SMEM_BYTES>>>(xt, swguT, hsbuf);
    mma_gemm<false, false><<<dim3(NTOK / 128, 8, 1), 256, SMEM_BYTES>>>(hsbuf, swdT, out);

    // routed experts
    mma_gemm<true, true><<<dim3(NTOK / 128, 8, E_NUM), 256, SMEM_BYTES>>>(xt, wguT, hbuf);
    mma_gemm<true, false><<<dim3(NTOK / 128, 8, E_NUM), 256, SMEM_BYTES>>>(hbuf, wdT, ybuf);

    combine_kernel<<<NTOK, 256>>>(out);
}